// round 6
// baseline (speedup 1.0000x reference)
#include <cuda_runtime.h>
#include <cstdint>

// ---------------------------------------------------------------------------
// NF4 block quant-dequant (blocksize 512), exact classification.
//
// Warp-register LUT (32 cells over [-1,1]): lane c holds the decision
// boundary inside cell c (or +1e30) and the codebook value at the cell's
// left edge. Lookup = FFMA cell index + 2 SHFLs + compare. Exact vs
// reference searchsorted.
//
// R5/R6: cp.async double-buffered pipeline. Each warp streams its next
// 512-float block into a private SMEM buffer (LDGSTS) while processing the
// current one. Latency lives in the async queue instead of registers ->
// high occupancy AND deep MLP. Warp-private buffers; lane i only reads
// bytes lane i copied, so no block-level syncs are needed.
// ---------------------------------------------------------------------------

#define QBLOCK 512
#define WARPS_PER_CTA 8
#define BLOCKS_PER_WARP 4

__constant__ float c_nf4[16] = {
    -1.0f, -0.6961928009986877f, -0.5250730514526367f, -0.39491748809814453f,
    -0.28444138169288635f, -0.18477343022823334f, -0.09105003625154495f, 0.0f,
    0.07958029955625534f, 0.16093020141124725f, 0.24611230194568634f,
    0.33791524171829224f, 0.4407098591327667f, 0.5626170039176941f,
    0.7229568362236023f, 1.0f
};

__device__ __forceinline__ void cp_async16(void* smem_dst, const void* gmem_src) {
    uint32_t sa = (uint32_t)__cvta_generic_to_shared(smem_dst);
    asm volatile("cp.async.cg.shared.global [%0], [%1], 16;" :: "r"(sa), "l"(gmem_src));
}

__global__ void __launch_bounds__(256, 4)
nf4_quant_dequant_kernel(const float* __restrict__ x,
                         float* __restrict__ out,
                         int n_qblocks) {
    __shared__ float buf[WARPS_PER_CTA][2][QBLOCK];

    const int lane   = threadIdx.x & 31;
    const int wlocal = threadIdx.x >> 5;

    // --- per-lane LUT cell (registers only) -------------------------------
    float mid_lane = 1e30f;
    float left_lane;
    {
        const float L = (float)lane * 0.0625f - 1.0f;
        const float R = L + 0.0625f;
        int idxL = 0;
#pragma unroll
        for (int i = 0; i < 15; i++) {
            float md = (c_nf4[i] + c_nf4[i + 1]) * 0.5f;   // fp32 == ref MID
            idxL += (md < L) ? 1 : 0;
            if (md > L && md < R) mid_lane = md;
        }
        left_lane = c_nf4[idxL];
    }

    const int warp = (blockIdx.x * blockDim.x + threadIdx.x) >> 5;
    const int base = warp * BLOCKS_PER_WARP;
    if (base >= n_qblocks) return;
    const int nb = min(BLOCKS_PER_WARP, n_qblocks - base);

    // lane-private slice of a stage buffer: floats lane*4 + k*128, k=0..3
#define PREFETCH(stage, b)                                                   \
    do {                                                                     \
        const float* _g = x + (size_t)(b) * QBLOCK + lane * 4;               \
        float* _s = &buf[wlocal][(stage)][lane * 4];                         \
        cp_async16(_s,       _g);                                            \
        cp_async16(_s + 128, _g + 128);                                      \
        cp_async16(_s + 256, _g + 256);                                      \
        cp_async16(_s + 384, _g + 384);                                      \
        asm volatile("cp.async.commit_group;");                              \
    } while (0)

    PREFETCH(0, base);

    for (int i = 0; i < nb; i++) {
        if (i + 1 < nb) {
            PREFETCH((i + 1) & 1, base + i + 1);
            asm volatile("cp.async.wait_group 1;");   // current buffer ready
        } else {
            asm volatile("cp.async.wait_group 0;");
        }
        __syncwarp();

        const float* s = &buf[wlocal][i & 1][0];
        float4 v0 = *(const float4*)(s + lane * 4);
        float4 v1 = *(const float4*)(s + lane * 4 + 128);
        float4 v2 = *(const float4*)(s + lane * 4 + 256);
        float4 v3 = *(const float4*)(s + lane * 4 + 384);

        float m;
        m = fabsf(v0.x);
        m = fmaxf(m, fabsf(v0.y)); m = fmaxf(m, fabsf(v0.z)); m = fmaxf(m, fabsf(v0.w));
        m = fmaxf(m, fabsf(v1.x)); m = fmaxf(m, fabsf(v1.y));
        m = fmaxf(m, fabsf(v1.z)); m = fmaxf(m, fabsf(v1.w));
        m = fmaxf(m, fabsf(v2.x)); m = fmaxf(m, fabsf(v2.y));
        m = fmaxf(m, fabsf(v2.z)); m = fmaxf(m, fabsf(v2.w));
        m = fmaxf(m, fabsf(v3.x)); m = fmaxf(m, fabsf(v3.y));
        m = fmaxf(m, fabsf(v3.z)); m = fmaxf(m, fabsf(v3.w));

#pragma unroll
        for (int off = 16; off > 0; off >>= 1)
            m = fmaxf(m, __shfl_xor_sync(0xffffffffu, m, off));

        const float scale    = (m == 0.0f) ? 1.0f : m;
        const float invscale = 1.0f / scale;   // one IEEE divide per block

        // exact: xn-space classification, identical to reference searchsorted
#define NF4_DEQ(val)                                                         \
        ({ float _xn = (val) * invscale;                                     \
           float _t  = fminf(fmaf(_xn, 16.0f, 16.0f), 31.0f);                \
           int _c = (int)_t;                                                 \
           float _mid = __shfl_sync(0xffffffffu, mid_lane, _c);              \
           _c += (_xn > _mid) ? 1 : 0;                                       \
           __shfl_sync(0xffffffffu, left_lane, _c) * m; })

        float4* d = (float4*)(out + (size_t)(base + i) * QBLOCK);
        float4 o;
        o.x = NF4_DEQ(v0.x); o.y = NF4_DEQ(v0.y);
        o.z = NF4_DEQ(v0.z); o.w = NF4_DEQ(v0.w);
        __stcs(d + lane, o);
        o.x = NF4_DEQ(v1.x); o.y = NF4_DEQ(v1.y);
        o.z = NF4_DEQ(v1.z); o.w = NF4_DEQ(v1.w);
        __stcs(d + lane + 32, o);
        o.x = NF4_DEQ(v2.x); o.y = NF4_DEQ(v2.y);
        o.z = NF4_DEQ(v2.z); o.w = NF4_DEQ(v2.w);
        __stcs(d + lane + 64, o);
        o.x = NF4_DEQ(v3.x); o.y = NF4_DEQ(v3.y);
        o.z = NF4_DEQ(v3.z); o.w = NF4_DEQ(v3.w);
        __stcs(d + lane + 96, o);
#undef NF4_DEQ
    }
#undef PREFETCH
}

extern "C" void kernel_launch(void* const* d_in, const int* in_sizes, int n_in,
                              void* d_out, int out_size) {
    const float* x = (const float*)d_in[0];
    float* out = (float*)d_out;
    const int n = in_sizes[0];
    const int n_qblocks = n / QBLOCK;   // 65536 for 4096x8192

    // 2048 CTAs x 8 warps = 16384 warps; each pipelines EXACTLY 4 blocks.
    const int ctas = (n_qblocks + WARPS_PER_CTA * BLOCKS_PER_WARP - 1) /
                     (WARPS_PER_CTA * BLOCKS_PER_WARP);
    nf4_quant_dequant_kernel<<<ctas, 32 * WARPS_PER_CTA>>>(x, out, n_qblocks);
}